// round 14
// baseline (speedup 1.0000x reference)
#include <cuda_runtime.h>
#include <cuda_bf16.h>
#include <cstdint>
#include <cstdio>
#include <cstring>
#include <math.h>

#define NW     8
#define QDIM   256
#define NRAND  20
#define NGATES 28
#define TPB    256
#define BSAMP  64
#define NSAMP  65536
#define KP     768      // augmented K': A=[Ah|Ah|Am], B=[Bh;Bm;Bh]

struct OpsParam { int kind[NGATES]; int wa[NGATES]; int wb[NGATES]; };

// B' matrix: [512 n][768 k'] bf16, n-major. k' 0..255 = Bh, 256..511 = Bm,
// 512..767 = Bh. n = 2*i + (0:re / 1:im), phase-folded.
__device__ __align__(16) __nv_bfloat16 g_Bp[512 * KP];

__device__ __forceinline__ void bsplit(float v, __nv_bfloat16& h, __nv_bfloat16& m) {
    h = __float2bfloat16(v);
    m = __float2bfloat16(v - __bfloat162float(h));
}

__device__ __forceinline__ void cp_async16(uint32_t smem_dst, const void* gsrc) {
    asm volatile("cp.async.cg.shared.global [%0], [%1], 16;" :: "r"(smem_dst), "l"(gsrc));
}
__device__ __forceinline__ void cp_async_commit() {
    asm volatile("cp.async.commit_group;");
}
template <int N>
__device__ __forceinline__ void cp_async_wait() {
    asm volatile("cp.async.wait_group %0;" :: "n"(N));
}

__device__ __forceinline__ void ldsm_x4(uint32_t& r0, uint32_t& r1,
                                        uint32_t& r2, uint32_t& r3, uint32_t addr) {
    asm volatile("ldmatrix.sync.aligned.m8n8.x4.shared.b16 {%0,%1,%2,%3}, [%4];"
                 : "=r"(r0), "=r"(r1), "=r"(r2), "=r"(r3) : "r"(addr));
}

__device__ __forceinline__ void mma_bf16(float* d, const uint32_t* a,
                                         uint32_t b0, uint32_t b1) {
    asm volatile(
        "mma.sync.aligned.m16n8k16.row.col.f32.bf16.bf16.f32 "
        "{%0,%1,%2,%3}, {%4,%5,%6,%7}, {%8,%9}, {%0,%1,%2,%3};"
        : "+f"(d[0]), "+f"(d[1]), "+f"(d[2]), "+f"(d[3])
        : "r"(a[0]), "r"(a[1]), "r"(a[2]), "r"(a[3]), "r"(b0), "r"(b1));
}

// ---------------------------------------------------------------------------
// Setup kernel (unchanged; passed R4-R13): builds g_Bp.
// ---------------------------------------------------------------------------
__global__ void build_W_kernel(const float* __restrict__ rx_params,
                               const float* __restrict__ random_params,
                               OpsParam ops) {
    __shared__ float2 st[QDIM];
    const int j   = blockIdx.x;
    const int tid = threadIdx.x;

    for (int idx = tid; idx < QDIM; idx += 128)
        st[idx] = make_float2(idx == j ? 1.0f : 0.0f, 0.0f);
    __syncthreads();

    for (int p = 0; p < NGATES; p++) {
        int g = ops.kind[p];
        if (g == 3) {
            int cm = 1 << (7 - ops.wa[p]);
            int tm = 1 << (7 - ops.wb[p]);
            for (int idx = tid; idx < QDIM; idx += 128) {
                if ((idx & cm) && !(idx & tm)) {
                    float2 t0 = st[idx];
                    st[idx] = st[idx | tm];
                    st[idx | tm] = t0;
                }
            }
        } else {
            float theta = (p < NRAND) ? random_params[p] : rx_params[p - NRAND];
            float h = 0.5f * theta;
            float c = cosf(h), s = sinf(h);
            int m  = 1 << (7 - ops.wa[p]);
            int t  = tid;
            int j0 = ((t & ~(m - 1)) << 1) | (t & (m - 1));
            int j1 = j0 | m;
            float2 v0 = st[j0], v1 = st[j1], n0, n1;
            if (g == 0) {
                n0 = make_float2(c * v0.x + s * v1.y, c * v0.y - s * v1.x);
                n1 = make_float2(c * v1.x + s * v0.y, c * v1.y - s * v0.x);
            } else if (g == 1) {
                n0 = make_float2(c * v0.x - s * v1.x, c * v0.y - s * v1.y);
                n1 = make_float2(s * v0.x + c * v1.x, s * v0.y + c * v1.y);
            } else {
                n0 = make_float2(c * v0.x + s * v0.y, c * v0.y - s * v0.x);
                n1 = make_float2(c * v1.x - s * v1.y, c * v1.y + s * v1.x);
            }
            st[j0] = n0;
            st[j1] = n1;
        }
        __syncthreads();
    }

    int pc = __popc(j) & 3;
    for (int i = tid; i < QDIM; i += 128) {
        float2 v = st[i];
        float re, im;
        if (pc == 0)      { re =  v.x; im =  v.y; }
        else if (pc == 1) { re =  v.y; im = -v.x; }
        else if (pc == 2) { re = -v.x; im = -v.y; }
        else              { re = -v.y; im =  v.x; }
        __nv_bfloat16 rh, rm, ih, im2;
        bsplit(re, rh, rm);
        bsplit(im, ih, im2);
        int nr = 2 * i, ni = 2 * i + 1;
        g_Bp[nr * KP + j]       = rh;
        g_Bp[nr * KP + 256 + j] = rm;
        g_Bp[nr * KP + 512 + j] = rh;
        g_Bp[ni * KP + j]       = ih;
        g_Bp[ni * KP + 256 + j] = im2;
        g_Bp[ni * KP + 512 + j] = ih;
    }
}

// ---------------------------------------------------------------------------
// Main kernel: 64 samples/block, 256 threads = 8 warps (2m x 4n),
// warp tile m32 x n64 (R12 shape: 192B smem per HMMA), two n-phases of 256,
// k-chunks of 32, SINGLE-SYNC pipeline (R13): 48 barriers/block.
// Smem: A[2][64][264] bf16 (66KB) + 2 B stages [256][40] bf16 (40KB)
//       + outs[64][8] f32 (2KB) = 109KB  -> 2 blocks/SM.
// ---------------------------------------------------------------------------
#define A_ROW    264
#define A_SELSZ  (BSAMP * A_ROW)
#define A_BYTES  (2 * A_SELSZ * 2)           // 67584
#define BT_ROW   40
#define BT_BYTES (256 * BT_ROW * 2)          // 20480
#define OUTS_OFF (A_BYTES + 2 * BT_BYTES)    // 108544
#define SMEM_BYTES (OUTS_OFF + BSAMP * 8 * 4)   // 110592

__global__ __launch_bounds__(TPB, 2)
void qsim_kernel(const float* __restrict__ x, float* __restrict__ out) {
    extern __shared__ char smem[];
    uint16_t* A = (uint16_t*)smem;
    float* outs = (float*)(smem + OUTS_OFF);             // [64][8]

    const uint32_t smem_u32 = (uint32_t)__cvta_generic_to_shared(smem);
    const uint32_t A_u32    = smem_u32;
    const uint32_t Bt_u32[2] = { smem_u32 + A_BYTES, smem_u32 + A_BYTES + BT_BYTES };
    uint16_t* Bt_gen[2] = { (uint16_t*)(smem + A_BYTES),
                            (uint16_t*)(smem + A_BYTES + BT_BYTES) };

    const int tid  = threadIdx.x;
    const int smp0 = blockIdx.x * BSAMP;

    if (tid < 128)
        ((float4*)outs)[tid] = make_float4(0.f, 0.f, 0.f, 0.f);

    // tile loader: phase nc, k' chunk kc (32 cols) for 256 n-rows
    auto issue_tile = [&](int nc, int kc, int buf) {
        const uint16_t* src =
            reinterpret_cast<const uint16_t*>(g_Bp) + (size_t)(nc * 256) * KP + kc * 32;
        uint16_t* dst = Bt_gen[buf];
#pragma unroll
        for (int c = 0; c < 4; c++) {
            int idx = tid + c * 256;          // 16B granule id, 0..1023
            int r = idx >> 2, gg = idx & 3;   // 4 granules per 32-k' row
            cp_async16((uint32_t)__cvta_generic_to_shared(dst + r * BT_ROW + gg * 8),
                       src + (size_t)r * KP + gg * 8);
        }
        cp_async_commit();
    };

    issue_tile(0, 0, 0);   // prefetch first tile; lands while we build A

    // ---- Phase 1: build A (4 threads per sample), bf16 split h/m ----
    {
        int s = tid >> 2, q = tid & 3;      // q = amplitude bits 7..6
        const float* xp = x + (size_t)(smp0 + s) * 8;
        float fc[8], fs[8];
#pragma unroll
        for (int w = 0; w < 8; w++) {
            float h = 0.5f * xp[w];
            fc[w] = cosf(h);
            fs[w] = sinf(h);
        }
        float f01 = ((q & 2) ? fs[0] : fc[0]) * ((q & 1) ? fs[1] : fc[1]);
#pragma unroll
        for (int jj = 0; jj < 64; jj++) {
            float r = f01;
            r *= (jj & 32) ? fs[2] : fc[2];
            r *= (jj & 16) ? fs[3] : fc[3];
            r *= (jj &  8) ? fs[4] : fc[4];
            r *= (jj &  4) ? fs[5] : fc[5];
            r *= (jj &  2) ? fs[6] : fc[6];
            r *= (jj &  1) ? fs[7] : fc[7];
            __nv_bfloat16 h, m;
            bsplit(r, h, m);
            int k = q * 64 + jj;
            A[0 * A_SELSZ + s * A_ROW + k] = ((uint16_t*)&h)[0];
            A[1 * A_SELSZ + s * A_ROW + k] = ((uint16_t*)&m)[0];
        }
    }

    const int lane = tid & 31;
    const int g = lane >> 2, t = lane & 3;
    const int wid = tid >> 5;
    const int wm = wid >> 2;          // 0..1  (m-rows wm*32)
    const int wn = wid & 3;           // 0..3  (n-cols wn*64 within phase)

    // lane-fixed pieces of ldmatrix addressing (R12 scheme, validated)
    const int a_rowlane = wm * 32 + (lane & 15);           // + mf*16
    const int a_collane = (lane >> 4) << 3;                // 0 or 8
    const int b_rowlane = wn * 64 + (lane & 7) + ((lane >> 4) << 3);  // + np*16
    const int b_collane = ((lane >> 3) & 1) << 3;          // 0 or 8

    const int NKC = KP / 32;   // 24 chunks per phase

    for (int nc = 0; nc < 2; nc++) {
        float acc[2][8][4];
#pragma unroll
        for (int mf = 0; mf < 2; mf++)
#pragma unroll
            for (int nf = 0; nf < 8; nf++)
#pragma unroll
                for (int d = 0; d < 4; d++) acc[mf][nf][d] = 0.0f;

        for (int kc = 0; kc < NKC; kc++) {
            cp_async_wait<0>();               // tile kc landed (this thread)
            __syncthreads();                  // all warps done with other buffer
            if (kc < NKC - 1)
                issue_tile(nc, kc + 1, (kc + 1) & 1);   // overlaps compute(kc)
            else if (nc < 1)
                issue_tile(nc + 1, 0, 0);               // prefetch next phase

            const uint32_t Bs = Bt_u32[kc & 1];
#pragma unroll
            for (int ks = 0; ks < 2; ks++) {
                const int k0g  = kc * 32 + ks * 16;
                const int asel = (k0g >= 512) ? 1 : 0;
                const int ak   = k0g & 255;

                uint32_t a[2][4];
#pragma unroll
                for (int mf = 0; mf < 2; mf++) {
                    uint32_t addr = A_u32 +
                        ((asel * A_SELSZ + (a_rowlane + mf * 16) * A_ROW + ak + a_collane) << 1);
                    ldsm_x4(a[mf][0], a[mf][1], a[mf][2], a[mf][3], addr);
                }
                uint32_t bf[4][4];
#pragma unroll
                for (int np = 0; np < 4; np++) {
                    uint32_t addr = Bs +
                        (((b_rowlane + np * 16) * BT_ROW + ks * 16 + b_collane) << 1);
                    ldsm_x4(bf[np][0], bf[np][1], bf[np][2], bf[np][3], addr);
                }
#pragma unroll
                for (int mf = 0; mf < 2; mf++)
#pragma unroll
                    for (int np = 0; np < 4; np++) {
                        mma_bf16(acc[mf][2 * np],     a[mf], bf[np][0], bf[np][1]);
                        mma_bf16(acc[mf][2 * np + 1], a[mf], bf[np][2], bf[np][3]);
                    }
            }
            // no trailing barrier: next iteration's top barrier protects reuse
        }

        // ---- epilogue: P = re^2+im^2, Walsh signs, reduce over t ----
        // (overlaps the async prefetch of the next phase's first tile)
#pragma unroll
        for (int mf = 0; mf < 2; mf++) {
            float oa[2][8];
#pragma unroll
            for (int r = 0; r < 2; r++)
#pragma unroll
                for (int k = 0; k < 8; k++) oa[r][k] = 0.0f;

#pragma unroll
            for (int nf = 0; nf < 8; nf++) {
                int i = nc * 128 + wn * 32 + nf * 4 + t;   // amplitude index
                float Pg  = acc[mf][nf][0] * acc[mf][nf][0] + acc[mf][nf][1] * acc[mf][nf][1];
                float Pg8 = acc[mf][nf][2] * acc[mf][nf][2] + acc[mf][nf][3] * acc[mf][nf][3];
#pragma unroll
                for (int k = 0; k < 8; k++) {
                    float s = ((i >> (7 - k)) & 1) ? -1.0f : 1.0f;
                    oa[0][k] += s * Pg;
                    oa[1][k] += s * Pg8;
                }
            }
#pragma unroll
            for (int r = 0; r < 2; r++)
#pragma unroll
                for (int k = 0; k < 8; k++) {
                    float v = oa[r][k];
                    v += __shfl_xor_sync(0xffffffffu, v, 1);
                    v += __shfl_xor_sync(0xffffffffu, v, 2);
                    if (t == 0) {
                        int row = wm * 32 + mf * 16 + g + 8 * r;
                        atomicAdd(&outs[row * 8 + k], v);
                    }
                }
        }
    }

    __syncthreads();
    if (tid < 128)
        ((float4*)(out + (size_t)smp0 * 8))[tid] = ((const float4*)outs)[tid];
}

// ---------------------------------------------------------------------------
// GATE_OPS via the exact reference mechanism (numpy subprocess). PASSED R4-R13.
// ---------------------------------------------------------------------------
static const char* PY_SNIPPET =
    "import numpy as np\n"
    "r = np.random.default_rng(42)\n"
    "for _ in range(20):\n"
    "    g = int(r.integers(0, 4))\n"
    "    if g == 3:\n"
    "        c, t = r.choice(8, size=2, replace=False)\n"
    "        print(3, int(c), int(t))\n"
    "    else:\n"
    "        print(g, int(r.integers(0, 8)), -1)\n";

static bool compute_gate_ops_python(OpsParam& ops, const char* interp) {
    char cmd[2048];
    snprintf(cmd, sizeof(cmd), "%s -c '%s' 2>/dev/null", interp, PY_SNIPPET);
    FILE* f = popen(cmd, "r");
    if (!f) return false;
    int n = 0;
    while (n < NRAND) {
        int g, a, b;
        if (fscanf(f, "%d %d %d", &g, &a, &b) != 3) break;
        if (g < 0 || g > 3 || a < 0 || a > 7 || (g == 3 && (b < 0 || b > 7))) break;
        ops.kind[n] = g; ops.wa[n] = a; ops.wb[n] = b;
        n++;
    }
    pclose(f);
    return n == NRAND;
}

namespace nprng {

struct PCG64 { __uint128_t state, inc; int has32; uint32_t buf32; };

static const __uint128_t PCG_MULT =
    (((__uint128_t)2549297995355413924ULL) << 64) | 4865540595714422341ULL;

static uint64_t next64(PCG64& r) {
    r.state = r.state * PCG_MULT + r.inc;
    uint64_t hi = (uint64_t)(r.state >> 64), lo = (uint64_t)r.state;
    uint64_t xv = hi ^ lo;
    unsigned rot = (unsigned)(r.state >> 122);
    return (xv >> rot) | (xv << ((64u - rot) & 63u));
}
static uint32_t next32(PCG64& r) {
    if (r.has32) { r.has32 = 0; return r.buf32; }
    uint64_t v = next64(r);
    r.has32 = 1;
    r.buf32 = (uint32_t)(v >> 32);
    return (uint32_t)v;
}
static void seedseq42(uint64_t out[4]) {
    const uint32_t XSH = 16;
    uint32_t pool[4];
    uint32_t hc = 0x43b0d7e5u;
    auto hashmix = [&](uint32_t v) {
        v ^= hc; hc *= 0x931e8875u; v *= hc; v ^= v >> XSH; return v;
    };
    auto mixf = [&](uint32_t xx, uint32_t yy) {
        uint32_t rr = (xx * 0xca01f9ddu) ^ (yy * 0x4973f715u);
        rr ^= rr >> XSH; return rr;
    };
    pool[0] = hashmix(42u);
    pool[1] = hashmix(0u);
    pool[2] = hashmix(0u);
    pool[3] = hashmix(0u);
    for (int src = 0; src < 4; src++)
        for (int dst = 0; dst < 4; dst++)
            if (src != dst) pool[dst] = mixf(pool[dst], hashmix(pool[src]));
    uint32_t hb = 0x8b51f9ddu;
    uint32_t w[8];
    for (int i = 0; i < 8; i++) {
        uint32_t v = pool[i & 3];
        v ^= hb; hb *= 0x58f38dedu; v *= hb; v ^= v >> XSH;
        w[i] = v;
    }
    for (int k = 0; k < 4; k++)
        out[k] = (uint64_t)w[2 * k] | ((uint64_t)w[2 * k + 1] << 32);
}
static void init42(PCG64& r) {
    uint64_t s4[4];
    seedseq42(s4);
    __uint128_t initstate = (((__uint128_t)s4[0]) << 64) | s4[1];
    __uint128_t initseq   = (((__uint128_t)s4[2]) << 64) | s4[3];
    r.state = 0;
    r.inc   = (initseq << 1) | 1;
    r.state = r.state * PCG_MULT + r.inc;
    r.state += initstate;
    r.state = r.state * PCG_MULT + r.inc;
    r.has32 = 0;
    r.buf32 = 0;
}
static uint64_t lemire32(PCG64& r, uint32_t rng) {
    uint32_t rng_excl = rng + 1;
    uint64_t m = (uint64_t)next32(r) * (uint64_t)rng_excl;
    uint32_t leftover = (uint32_t)m;
    if (leftover < rng_excl) {
        uint32_t threshold = (uint32_t)((0xFFFFFFFFu - rng) % rng_excl);
        while (leftover < threshold) {
            m = (uint64_t)next32(r) * (uint64_t)rng_excl;
            leftover = (uint32_t)m;
        }
    }
    return (uint64_t)(m >> 32);
}
} // namespace nprng

static void compute_gate_ops_cpp(OpsParam& ops) {
    nprng::PCG64 r;
    nprng::init42(r);
    for (int p = 0; p < NRAND; p++) {
        int g = (int)nprng::lemire32(r, 3);
        if (g == 3) {
            uint64_t v6 = nprng::lemire32(r, 6);
            uint64_t v7 = nprng::lemire32(r, 7);
            uint64_t i0 = v6;
            uint64_t i1 = (v7 == v6) ? 7 : v7;
            uint64_t js = nprng::lemire32(r, 1);
            if (js == 0) { uint64_t t = i0; i0 = i1; i1 = t; }
            ops.kind[p] = 3;
            ops.wa[p] = (int)i0;
            ops.wb[p] = (int)i1;
        } else {
            ops.kind[p] = g;
            ops.wa[p] = (int)nprng::lemire32(r, 7);
            ops.wb[p] = -1;
        }
    }
}

extern "C" void kernel_launch(void* const* d_in, const int* in_sizes, int n_in,
                              void* d_out, int out_size) {
    const float* x  = nullptr;
    const float* rx = nullptr;
    const float* rp = nullptr;
    for (int i = 0; i < n_in; i++) {
        if (in_sizes[i] == 8)       rx = (const float*)d_in[i];
        else if (in_sizes[i] == 20) rp = (const float*)d_in[i];
        else                        x  = (const float*)d_in[i];
    }
    if (!x)  x  = (const float*)d_in[0];
    if (!rx) rx = (const float*)d_in[1];
    if (!rp) rp = (const float*)d_in[2];
    float* out = (float*)d_out;
    (void)out_size;

    OpsParam ops;
    bool ok = compute_gate_ops_python(ops, "python3");
    if (!ok) ok = compute_gate_ops_python(ops, "python");
    if (!ok) {
        fprintf(stderr, "[qsim] python GATE_OPS derivation FAILED -> C++ fallback\n");
        compute_gate_ops_cpp(ops);
    }

    for (int w = 0; w < 8; w++) {
        ops.kind[NRAND + w] = 0;
        ops.wa[NRAND + w] = w;
        ops.wb[NRAND + w] = -1;
    }

    cudaFuncSetAttribute(qsim_kernel, cudaFuncAttributeMaxDynamicSharedMemorySize,
                         SMEM_BYTES);

    build_W_kernel<<<QDIM, 128>>>(rx, rp, ops);
    qsim_kernel<<<NSAMP / BSAMP, TPB, SMEM_BYTES>>>(x, out);
}

// round 15
// speedup vs baseline: 1.1016x; 1.1016x over previous
#include <cuda_runtime.h>
#include <cuda_bf16.h>
#include <cstdint>
#include <cstdio>
#include <cstring>
#include <math.h>

#define NW     8
#define QDIM   256
#define NRAND  20
#define NGATES 28
#define TPB    256
#define BSAMP  64
#define NSAMP  65536
#define KP     768      // augmented K': A=[Ah|Ah|Am], B=[Bh;Bm;Bh]

struct OpsParam { int kind[NGATES]; int wa[NGATES]; int wb[NGATES]; };

// B' matrix: [512 n][768 k'] bf16, n-major. k' 0..255 = Bh, 256..511 = Bm,
// 512..767 = Bh. n = 2*i + (0:re / 1:im), phase-folded.
__device__ __align__(16) __nv_bfloat16 g_Bp[512 * KP];

__device__ __forceinline__ void bsplit(float v, __nv_bfloat16& h, __nv_bfloat16& m) {
    h = __float2bfloat16(v);
    m = __float2bfloat16(v - __bfloat162float(h));
}

__device__ __forceinline__ void cp_async16(uint32_t smem_dst, const void* gsrc) {
    asm volatile("cp.async.cg.shared.global [%0], [%1], 16;" :: "r"(smem_dst), "l"(gsrc));
}
__device__ __forceinline__ void cp_async_commit() {
    asm volatile("cp.async.commit_group;");
}
template <int N>
__device__ __forceinline__ void cp_async_wait() {
    asm volatile("cp.async.wait_group %0;" :: "n"(N));
}

__device__ __forceinline__ void ldsm_x4(uint32_t& r0, uint32_t& r1,
                                        uint32_t& r2, uint32_t& r3, uint32_t addr) {
    asm volatile("ldmatrix.sync.aligned.m8n8.x4.shared.b16 {%0,%1,%2,%3}, [%4];"
                 : "=r"(r0), "=r"(r1), "=r"(r2), "=r"(r3) : "r"(addr));
}

__device__ __forceinline__ void mma_bf16(float* d, const uint32_t* a,
                                         uint32_t b0, uint32_t b1) {
    asm volatile(
        "mma.sync.aligned.m16n8k16.row.col.f32.bf16.bf16.f32 "
        "{%0,%1,%2,%3}, {%4,%5,%6,%7}, {%8,%9}, {%0,%1,%2,%3};"
        : "+f"(d[0]), "+f"(d[1]), "+f"(d[2]), "+f"(d[3])
        : "r"(a[0]), "r"(a[1]), "r"(a[2]), "r"(a[3]), "r"(b0), "r"(b1));
}

// ---------------------------------------------------------------------------
// Setup kernel (unchanged; passed R4-R14): builds g_Bp.
// ---------------------------------------------------------------------------
__global__ void build_W_kernel(const float* __restrict__ rx_params,
                               const float* __restrict__ random_params,
                               OpsParam ops) {
    __shared__ float2 st[QDIM];
    const int j   = blockIdx.x;
    const int tid = threadIdx.x;

    for (int idx = tid; idx < QDIM; idx += 128)
        st[idx] = make_float2(idx == j ? 1.0f : 0.0f, 0.0f);
    __syncthreads();

    for (int p = 0; p < NGATES; p++) {
        int g = ops.kind[p];
        if (g == 3) {
            int cm = 1 << (7 - ops.wa[p]);
            int tm = 1 << (7 - ops.wb[p]);
            for (int idx = tid; idx < QDIM; idx += 128) {
                if ((idx & cm) && !(idx & tm)) {
                    float2 t0 = st[idx];
                    st[idx] = st[idx | tm];
                    st[idx | tm] = t0;
                }
            }
        } else {
            float theta = (p < NRAND) ? random_params[p] : rx_params[p - NRAND];
            float h = 0.5f * theta;
            float c = cosf(h), s = sinf(h);
            int m  = 1 << (7 - ops.wa[p]);
            int t  = tid;
            int j0 = ((t & ~(m - 1)) << 1) | (t & (m - 1));
            int j1 = j0 | m;
            float2 v0 = st[j0], v1 = st[j1], n0, n1;
            if (g == 0) {
                n0 = make_float2(c * v0.x + s * v1.y, c * v0.y - s * v1.x);
                n1 = make_float2(c * v1.x + s * v0.y, c * v1.y - s * v0.x);
            } else if (g == 1) {
                n0 = make_float2(c * v0.x - s * v1.x, c * v0.y - s * v1.y);
                n1 = make_float2(s * v0.x + c * v1.x, s * v0.y + c * v1.y);
            } else {
                n0 = make_float2(c * v0.x + s * v0.y, c * v0.y - s * v0.x);
                n1 = make_float2(c * v1.x - s * v1.y, c * v1.y + s * v1.x);
            }
            st[j0] = n0;
            st[j1] = n1;
        }
        __syncthreads();
    }

    int pc = __popc(j) & 3;
    for (int i = tid; i < QDIM; i += 128) {
        float2 v = st[i];
        float re, im;
        if (pc == 0)      { re =  v.x; im =  v.y; }
        else if (pc == 1) { re =  v.y; im = -v.x; }
        else if (pc == 2) { re = -v.x; im = -v.y; }
        else              { re = -v.y; im =  v.x; }
        __nv_bfloat16 rh, rm, ih, im2;
        bsplit(re, rh, rm);
        bsplit(im, ih, im2);
        int nr = 2 * i, ni = 2 * i + 1;
        g_Bp[nr * KP + j]       = rh;
        g_Bp[nr * KP + 256 + j] = rm;
        g_Bp[nr * KP + 512 + j] = rh;
        g_Bp[ni * KP + j]       = ih;
        g_Bp[ni * KP + 256 + j] = im2;
        g_Bp[ni * KP + 512 + j] = ih;
    }
}

// ---------------------------------------------------------------------------
// Main kernel: R13 winner (m32 x n32, 4 n-phases, 64-k' chunks, single-sync
// pipeline, 48 barriers) + explicit fragment double-buffering in the ks loop.
// Smem: A[2][64][264] bf16 (66KB) + 2 B stages [128][72] bf16 (36KB)
//       + outs[4][64][8] f32 (8KB) = 110KB  -> 2 blocks/SM.
// ---------------------------------------------------------------------------
#define A_ROW    264
#define A_SELSZ  (BSAMP * A_ROW)
#define A_BYTES  (2 * A_SELSZ * 2)           // 67584
#define BT_ROW   72
#define BT_BYTES (128 * BT_ROW * 2)          // 18432
#define OUTS_OFF (A_BYTES + 2 * BT_BYTES)    // 104448
#define SMEM_BYTES (OUTS_OFF + 4 * BSAMP * 8 * 4)   // 112640

__global__ __launch_bounds__(TPB, 2)
void qsim_kernel(const float* __restrict__ x, float* __restrict__ out) {
    extern __shared__ char smem[];
    uint16_t* A = (uint16_t*)smem;
    float* outs = (float*)(smem + OUTS_OFF);             // [4 wn][64][8]

    const uint32_t smem_u32 = (uint32_t)__cvta_generic_to_shared(smem);
    const uint32_t A_u32    = smem_u32;
    const uint32_t Bt_u32[2] = { smem_u32 + A_BYTES, smem_u32 + A_BYTES + BT_BYTES };
    uint16_t* Bt_gen[2] = { (uint16_t*)(smem + A_BYTES),
                            (uint16_t*)(smem + A_BYTES + BT_BYTES) };

    const int tid  = threadIdx.x;
    const int smp0 = blockIdx.x * BSAMP;

#pragma unroll
    for (int z = 0; z < 2; z++)
        ((float4*)outs)[tid + z * 256] = make_float4(0.f, 0.f, 0.f, 0.f);

    // tile loader: phase nc, k' chunk kc (64 cols) for 128 n-rows
    auto issue_tile = [&](int nc, int kc, int buf) {
        const uint16_t* src =
            reinterpret_cast<const uint16_t*>(g_Bp) + (size_t)(nc * 128) * KP + kc * 64;
        uint16_t* dst = Bt_gen[buf];
#pragma unroll
        for (int c = 0; c < 4; c++) {
            int idx = tid + c * 256;          // 16B granule id, 0..1023
            int r = idx >> 3, gg = idx & 7;
            cp_async16((uint32_t)__cvta_generic_to_shared(dst + r * BT_ROW + gg * 8),
                       src + (size_t)r * KP + gg * 8);
        }
        cp_async_commit();
    };

    issue_tile(0, 0, 0);   // prefetch first tile; lands while we build A

    // ---- Phase 1: build A (4 threads per sample), bf16 split h/m ----
    {
        int s = tid >> 2, q = tid & 3;      // q = amplitude bits 7..6
        const float* xp = x + (size_t)(smp0 + s) * 8;
        float fc[8], fs[8];
#pragma unroll
        for (int w = 0; w < 8; w++) {
            float h = 0.5f * xp[w];
            fc[w] = cosf(h);
            fs[w] = sinf(h);
        }
        float f01 = ((q & 2) ? fs[0] : fc[0]) * ((q & 1) ? fs[1] : fc[1]);
#pragma unroll
        for (int jj = 0; jj < 64; jj++) {
            float r = f01;
            r *= (jj & 32) ? fs[2] : fc[2];
            r *= (jj & 16) ? fs[3] : fc[3];
            r *= (jj &  8) ? fs[4] : fc[4];
            r *= (jj &  4) ? fs[5] : fc[5];
            r *= (jj &  2) ? fs[6] : fc[6];
            r *= (jj &  1) ? fs[7] : fc[7];
            __nv_bfloat16 h, m;
            bsplit(r, h, m);
            int k = q * 64 + jj;
            A[0 * A_SELSZ + s * A_ROW + k] = ((uint16_t*)&h)[0];
            A[1 * A_SELSZ + s * A_ROW + k] = ((uint16_t*)&m)[0];
        }
    }

    const int lane = tid & 31;
    const int g = lane >> 2, t = lane & 3;
    const int wid = tid >> 5;
    const int wm = wid >> 2;          // 0..1  (m-rows wm*32)
    const int wn = wid & 3;           // 0..3  (n-cols wn*32 within phase)

    // lane-fixed pieces of ldmatrix addressing (passed R8/R10/R11/R13)
    const int a_rowlane = wm * 32 + (lane & 15);           // + mf*16
    const int a_collane = (lane >> 4) << 3;                // 0 or 8
    const int b_rowlane = wn * 32 + (lane & 7) + ((lane >> 4) << 3);  // + np*16
    const int b_collane = ((lane >> 3) & 1) << 3;          // 0 or 8

    const int NKC = KP / 64;   // 12

    for (int nc = 0; nc < 4; nc++) {
        float acc[2][4][4];
#pragma unroll
        for (int mf = 0; mf < 2; mf++)
#pragma unroll
            for (int nf = 0; nf < 4; nf++)
#pragma unroll
                for (int d = 0; d < 4; d++) acc[mf][nf][d] = 0.0f;

        for (int kc = 0; kc < NKC; kc++) {
            cp_async_wait<0>();               // tile kc landed (this thread)
            __syncthreads();                  // all warps done with other buffer
            if (kc < NKC - 1)
                issue_tile(nc, kc + 1, (kc + 1) & 1);   // overlaps compute(kc)
            else if (nc < 3)
                issue_tile(nc + 1, 0, 0);               // prefetch next phase

            const uint32_t Bs = Bt_u32[kc & 1];
            // asel constant within a 64-k' chunk (512 boundary chunk-aligned)
            const int asel = (kc >= 8) ? 1 : 0;
            const uint32_t Abase = A_u32 + ((asel * A_SELSZ) << 1);

            // ---- ks loop with explicit fragment double-buffering ----
            uint32_t afr[2][2][4];    // [buf][mf][4]
            uint32_t bfr[2][2][4];    // [buf][np][4]

            {   // preload ks=0
                const int ak = (kc * 64) & 255;
#pragma unroll
                for (int mf = 0; mf < 2; mf++) {
                    uint32_t addr = Abase +
                        (((a_rowlane + mf * 16) * A_ROW + ak + a_collane) << 1);
                    ldsm_x4(afr[0][mf][0], afr[0][mf][1], afr[0][mf][2], afr[0][mf][3], addr);
                }
#pragma unroll
                for (int np = 0; np < 2; np++) {
                    uint32_t addr = Bs +
                        (((b_rowlane + np * 16) * BT_ROW + b_collane) << 1);
                    ldsm_x4(bfr[0][np][0], bfr[0][np][1], bfr[0][np][2], bfr[0][np][3], addr);
                }
            }

#pragma unroll
            for (int ks = 0; ks < 4; ks++) {
                const int cur = ks & 1;
                if (ks < 3) {
                    const int nxt = (ks + 1) & 1;
                    const int ak = (kc * 64 + (ks + 1) * 16) & 255;
#pragma unroll
                    for (int mf = 0; mf < 2; mf++) {
                        uint32_t addr = Abase +
                            (((a_rowlane + mf * 16) * A_ROW + ak + a_collane) << 1);
                        ldsm_x4(afr[nxt][mf][0], afr[nxt][mf][1],
                                afr[nxt][mf][2], afr[nxt][mf][3], addr);
                    }
#pragma unroll
                    for (int np = 0; np < 2; np++) {
                        uint32_t addr = Bs +
                            (((b_rowlane + np * 16) * BT_ROW + (ks + 1) * 16 + b_collane) << 1);
                        ldsm_x4(bfr[nxt][np][0], bfr[nxt][np][1],
                                bfr[nxt][np][2], bfr[nxt][np][3], addr);
                    }
                }
#pragma unroll
                for (int mf = 0; mf < 2; mf++)
#pragma unroll
                    for (int np = 0; np < 2; np++) {
                        mma_bf16(acc[mf][2 * np],     afr[cur][mf], bfr[cur][np][0], bfr[cur][np][1]);
                        mma_bf16(acc[mf][2 * np + 1], afr[cur][mf], bfr[cur][np][2], bfr[cur][np][3]);
                    }
            }
            // no trailing barrier: next iteration's top barrier protects reuse
        }

        // ---- epilogue: P = re^2+im^2, Walsh signs, reduce over t ----
        // (overlaps the async prefetch of the next phase's first tile)
#pragma unroll
        for (int mf = 0; mf < 2; mf++) {
            float oa[2][8];
#pragma unroll
            for (int r = 0; r < 2; r++)
#pragma unroll
                for (int k = 0; k < 8; k++) oa[r][k] = 0.0f;

#pragma unroll
            for (int nf = 0; nf < 4; nf++) {
                int i = nc * 64 + wn * 16 + nf * 4 + t;   // amplitude index
                float Pg  = acc[mf][nf][0] * acc[mf][nf][0] + acc[mf][nf][1] * acc[mf][nf][1];
                float Pg8 = acc[mf][nf][2] * acc[mf][nf][2] + acc[mf][nf][3] * acc[mf][nf][3];
#pragma unroll
                for (int k = 0; k < 8; k++) {
                    float s = ((i >> (7 - k)) & 1) ? -1.0f : 1.0f;
                    oa[0][k] += s * Pg;
                    oa[1][k] += s * Pg8;
                }
            }
#pragma unroll
            for (int r = 0; r < 2; r++)
#pragma unroll
                for (int k = 0; k < 8; k++) {
                    float v = oa[r][k];
                    v += __shfl_xor_sync(0xffffffffu, v, 1);
                    v += __shfl_xor_sync(0xffffffffu, v, 2);
                    if (t == 0) {
                        int row = wm * 32 + mf * 16 + g + 8 * r;
                        outs[(wn * BSAMP + row) * 8 + k] += v;   // unique writer
                    }
                }
        }
    }

    __syncthreads();
    // sum 4 wn-partials, write out (threads 0..127, one float4 each)
    if (tid < 128) {
        float4 v0 = ((const float4*)outs)[tid];
        float4 v1 = ((const float4*)outs)[tid + 128];
        float4 v2 = ((const float4*)outs)[tid + 256];
        float4 v3 = ((const float4*)outs)[tid + 384];
        float4 v = make_float4(v0.x + v1.x + v2.x + v3.x,
                               v0.y + v1.y + v2.y + v3.y,
                               v0.z + v1.z + v2.z + v3.z,
                               v0.w + v1.w + v2.w + v3.w);
        ((float4*)(out + (size_t)smp0 * 8))[tid] = v;
    }
}

// ---------------------------------------------------------------------------
// GATE_OPS via the exact reference mechanism (numpy subprocess). PASSED R4-R14.
// ---------------------------------------------------------------------------
static const char* PY_SNIPPET =
    "import numpy as np\n"
    "r = np.random.default_rng(42)\n"
    "for _ in range(20):\n"
    "    g = int(r.integers(0, 4))\n"
    "    if g == 3:\n"
    "        c, t = r.choice(8, size=2, replace=False)\n"
    "        print(3, int(c), int(t))\n"
    "    else:\n"
    "        print(g, int(r.integers(0, 8)), -1)\n";

static bool compute_gate_ops_python(OpsParam& ops, const char* interp) {
    char cmd[2048];
    snprintf(cmd, sizeof(cmd), "%s -c '%s' 2>/dev/null", interp, PY_SNIPPET);
    FILE* f = popen(cmd, "r");
    if (!f) return false;
    int n = 0;
    while (n < NRAND) {
        int g, a, b;
        if (fscanf(f, "%d %d %d", &g, &a, &b) != 3) break;
        if (g < 0 || g > 3 || a < 0 || a > 7 || (g == 3 && (b < 0 || b > 7))) break;
        ops.kind[n] = g; ops.wa[n] = a; ops.wb[n] = b;
        n++;
    }
    pclose(f);
    return n == NRAND;
}

namespace nprng {

struct PCG64 { __uint128_t state, inc; int has32; uint32_t buf32; };

static const __uint128_t PCG_MULT =
    (((__uint128_t)2549297995355413924ULL) << 64) | 4865540595714422341ULL;

static uint64_t next64(PCG64& r) {
    r.state = r.state * PCG_MULT + r.inc;
    uint64_t hi = (uint64_t)(r.state >> 64), lo = (uint64_t)r.state;
    uint64_t xv = hi ^ lo;
    unsigned rot = (unsigned)(r.state >> 122);
    return (xv >> rot) | (xv << ((64u - rot) & 63u));
}
static uint32_t next32(PCG64& r) {
    if (r.has32) { r.has32 = 0; return r.buf32; }
    uint64_t v = next64(r);
    r.has32 = 1;
    r.buf32 = (uint32_t)(v >> 32);
    return (uint32_t)v;
}
static void seedseq42(uint64_t out[4]) {
    const uint32_t XSH = 16;
    uint32_t pool[4];
    uint32_t hc = 0x43b0d7e5u;
    auto hashmix = [&](uint32_t v) {
        v ^= hc; hc *= 0x931e8875u; v *= hc; v ^= v >> XSH; return v;
    };
    auto mixf = [&](uint32_t xx, uint32_t yy) {
        uint32_t rr = (xx * 0xca01f9ddu) ^ (yy * 0x4973f715u);
        rr ^= rr >> XSH; return rr;
    };
    pool[0] = hashmix(42u);
    pool[1] = hashmix(0u);
    pool[2] = hashmix(0u);
    pool[3] = hashmix(0u);
    for (int src = 0; src < 4; src++)
        for (int dst = 0; dst < 4; dst++)
            if (src != dst) pool[dst] = mixf(pool[dst], hashmix(pool[src]));
    uint32_t hb = 0x8b51f9ddu;
    uint32_t w[8];
    for (int i = 0; i < 8; i++) {
        uint32_t v = pool[i & 3];
        v ^= hb; hb *= 0x58f38dedu; v *= hb; v ^= v >> XSH;
        w[i] = v;
    }
    for (int k = 0; k < 4; k++)
        out[k] = (uint64_t)w[2 * k] | ((uint64_t)w[2 * k + 1] << 32);
}
static void init42(PCG64& r) {
    uint64_t s4[4];
    seedseq42(s4);
    __uint128_t initstate = (((__uint128_t)s4[0]) << 64) | s4[1];
    __uint128_t initseq   = (((__uint128_t)s4[2]) << 64) | s4[3];
    r.state = 0;
    r.inc   = (initseq << 1) | 1;
    r.state = r.state * PCG_MULT + r.inc;
    r.state += initstate;
    r.state = r.state * PCG_MULT + r.inc;
    r.has32 = 0;
    r.buf32 = 0;
}
static uint64_t lemire32(PCG64& r, uint32_t rng) {
    uint32_t rng_excl = rng + 1;
    uint64_t m = (uint64_t)next32(r) * (uint64_t)rng_excl;
    uint32_t leftover = (uint32_t)m;
    if (leftover < rng_excl) {
        uint32_t threshold = (uint32_t)((0xFFFFFFFFu - rng) % rng_excl);
        while (leftover < threshold) {
            m = (uint64_t)next32(r) * (uint64_t)rng_excl;
            leftover = (uint32_t)m;
        }
    }
    return (uint64_t)(m >> 32);
}
} // namespace nprng

static void compute_gate_ops_cpp(OpsParam& ops) {
    nprng::PCG64 r;
    nprng::init42(r);
    for (int p = 0; p < NRAND; p++) {
        int g = (int)nprng::lemire32(r, 3);
        if (g == 3) {
            uint64_t v6 = nprng::lemire32(r, 6);
            uint64_t v7 = nprng::lemire32(r, 7);
            uint64_t i0 = v6;
            uint64_t i1 = (v7 == v6) ? 7 : v7;
            uint64_t js = nprng::lemire32(r, 1);
            if (js == 0) { uint64_t t = i0; i0 = i1; i1 = t; }
            ops.kind[p] = 3;
            ops.wa[p] = (int)i0;
            ops.wb[p] = (int)i1;
        } else {
            ops.kind[p] = g;
            ops.wa[p] = (int)nprng::lemire32(r, 7);
            ops.wb[p] = -1;
        }
    }
}

extern "C" void kernel_launch(void* const* d_in, const int* in_sizes, int n_in,
                              void* d_out, int out_size) {
    const float* x  = nullptr;
    const float* rx = nullptr;
    const float* rp = nullptr;
    for (int i = 0; i < n_in; i++) {
        if (in_sizes[i] == 8)       rx = (const float*)d_in[i];
        else if (in_sizes[i] == 20) rp = (const float*)d_in[i];
        else                        x  = (const float*)d_in[i];
    }
    if (!x)  x  = (const float*)d_in[0];
    if (!rx) rx = (const float*)d_in[1];
    if (!rp) rp = (const float*)d_in[2];
    float* out = (float*)d_out;
    (void)out_size;

    OpsParam ops;
    bool ok = compute_gate_ops_python(ops, "python3");
    if (!ok) ok = compute_gate_ops_python(ops, "python");
    if (!ok) {
        fprintf(stderr, "[qsim] python GATE_OPS derivation FAILED -> C++ fallback\n");
        compute_gate_ops_cpp(ops);
    }

    for (int w = 0; w < 8; w++) {
        ops.kind[NRAND + w] = 0;
        ops.wa[NRAND + w] = w;
        ops.wb[NRAND + w] = -1;
    }

    cudaFuncSetAttribute(qsim_kernel, cudaFuncAttributeMaxDynamicSharedMemorySize,
                         SMEM_BYTES);

    build_W_kernel<<<QDIM, 128>>>(rx, rp, ops);
    qsim_kernel<<<NSAMP / BSAMP, TPB, SMEM_BYTES>>>(x, out);
}

// round 16
// speedup vs baseline: 1.1481x; 1.0422x over previous
#include <cuda_runtime.h>
#include <cuda_bf16.h>
#include <cstdint>
#include <cstdio>
#include <cstring>
#include <math.h>

#define NW     8
#define QDIM   256
#define NRAND  20
#define NGATES 28
#define TPB    256
#define BSAMP  64
#define NSAMP  65536
#define KP     768      // augmented K': A=[Ah|Am], B cols: [Bh|Bm interleaved | Bh]

struct OpsParam { int kind[NGATES]; int wa[NGATES]; int wb[NGATES]; };

// B' matrix: [512 n][768 k'] bf16, n-major.
// Cols 0..511: for k-block kb (0..7, 32 k each): cols 64kb..64kb+31 = Bh(k),
//              cols 64kb+32..64kb+63 = Bm(k)  [interleaved so A frags are shared]
// Cols 512..767: Bh(k) again (for the Am*Bh pass).
// n = 2*i + (0:re / 1:im), phase-folded.
__device__ __align__(16) __nv_bfloat16 g_Bp[512 * KP];

__device__ __forceinline__ void bsplit(float v, __nv_bfloat16& h, __nv_bfloat16& m) {
    h = __float2bfloat16(v);
    m = __float2bfloat16(v - __bfloat162float(h));
}

__device__ __forceinline__ void cp_async16(uint32_t smem_dst, const void* gsrc) {
    asm volatile("cp.async.cg.shared.global [%0], [%1], 16;" :: "r"(smem_dst), "l"(gsrc));
}
__device__ __forceinline__ void cp_async_commit() {
    asm volatile("cp.async.commit_group;");
}
template <int N>
__device__ __forceinline__ void cp_async_wait() {
    asm volatile("cp.async.wait_group %0;" :: "n"(N));
}

__device__ __forceinline__ void ldsm_x4(uint32_t& r0, uint32_t& r1,
                                        uint32_t& r2, uint32_t& r3, uint32_t addr) {
    asm volatile("ldmatrix.sync.aligned.m8n8.x4.shared.b16 {%0,%1,%2,%3}, [%4];"
                 : "=r"(r0), "=r"(r1), "=r"(r2), "=r"(r3) : "r"(addr));
}

__device__ __forceinline__ void mma_bf16(float* d, const uint32_t* a,
                                         uint32_t b0, uint32_t b1) {
    asm volatile(
        "mma.sync.aligned.m16n8k16.row.col.f32.bf16.bf16.f32 "
        "{%0,%1,%2,%3}, {%4,%5,%6,%7}, {%8,%9}, {%0,%1,%2,%3};"
        : "+f"(d[0]), "+f"(d[1]), "+f"(d[2]), "+f"(d[3])
        : "r"(a[0]), "r"(a[1]), "r"(a[2]), "r"(a[3]), "r"(b0), "r"(b1));
}

// ---------------------------------------------------------------------------
// Setup kernel (circuit part unchanged, passed R4-R15): builds g_Bp with the
// NEW interleaved column layout.
// ---------------------------------------------------------------------------
__global__ void build_W_kernel(const float* __restrict__ rx_params,
                               const float* __restrict__ random_params,
                               OpsParam ops) {
    __shared__ float2 st[QDIM];
    const int j   = blockIdx.x;
    const int tid = threadIdx.x;

    for (int idx = tid; idx < QDIM; idx += 128)
        st[idx] = make_float2(idx == j ? 1.0f : 0.0f, 0.0f);
    __syncthreads();

    for (int p = 0; p < NGATES; p++) {
        int g = ops.kind[p];
        if (g == 3) {
            int cm = 1 << (7 - ops.wa[p]);
            int tm = 1 << (7 - ops.wb[p]);
            for (int idx = tid; idx < QDIM; idx += 128) {
                if ((idx & cm) && !(idx & tm)) {
                    float2 t0 = st[idx];
                    st[idx] = st[idx | tm];
                    st[idx | tm] = t0;
                }
            }
        } else {
            float theta = (p < NRAND) ? random_params[p] : rx_params[p - NRAND];
            float h = 0.5f * theta;
            float c = cosf(h), s = sinf(h);
            int m  = 1 << (7 - ops.wa[p]);
            int t  = tid;
            int j0 = ((t & ~(m - 1)) << 1) | (t & (m - 1));
            int j1 = j0 | m;
            float2 v0 = st[j0], v1 = st[j1], n0, n1;
            if (g == 0) {
                n0 = make_float2(c * v0.x + s * v1.y, c * v0.y - s * v1.x);
                n1 = make_float2(c * v1.x + s * v0.y, c * v1.y - s * v0.x);
            } else if (g == 1) {
                n0 = make_float2(c * v0.x - s * v1.x, c * v0.y - s * v1.y);
                n1 = make_float2(s * v0.x + c * v1.x, s * v0.y + c * v1.y);
            } else {
                n0 = make_float2(c * v0.x + s * v0.y, c * v0.y - s * v0.x);
                n1 = make_float2(c * v1.x - s * v1.y, c * v1.y + s * v1.x);
            }
            st[j0] = n0;
            st[j1] = n1;
        }
        __syncthreads();
    }

    int pc = __popc(j) & 3;
    // interleaved layout: k-block kb = j>>5; within-block kk = j&31
    const int col_h = ((j >> 5) << 6) + (j & 31);        // Bh column
    const int col_m = col_h + 32;                        // Bm column
    for (int i = tid; i < QDIM; i += 128) {
        float2 v = st[i];
        float re, im;
        if (pc == 0)      { re =  v.x; im =  v.y; }
        else if (pc == 1) { re =  v.y; im = -v.x; }
        else if (pc == 2) { re = -v.x; im = -v.y; }
        else              { re = -v.y; im =  v.x; }
        __nv_bfloat16 rh, rm, ih, im2;
        bsplit(re, rh, rm);
        bsplit(im, ih, im2);
        int nr = 2 * i, ni = 2 * i + 1;
        g_Bp[nr * KP + col_h]    = rh;
        g_Bp[nr * KP + col_m]    = rm;
        g_Bp[nr * KP + 512 + j]  = rh;
        g_Bp[ni * KP + col_h]    = ih;
        g_Bp[ni * KP + col_m]    = im2;
        g_Bp[ni * KP + 512 + j]  = ih;
    }
}

// ---------------------------------------------------------------------------
// Main kernel: R13 winner (m32 x n32, 4 n-phases, 64-k' chunks, single-sync
// pipeline, 48 barriers) + A-fragment sharing via interleaved B columns:
// chunks 0..7 load A once per 32-k block and reuse it for both Bh and Bm.
// Smem: A[2][64][264] bf16 (66KB) + 2 B stages [128][72] bf16 (36KB)
//       + outs[4][64][8] f32 (8KB) = 110KB  -> 2 blocks/SM.
// ---------------------------------------------------------------------------
#define A_ROW    264
#define A_SELSZ  (BSAMP * A_ROW)
#define A_BYTES  (2 * A_SELSZ * 2)           // 67584
#define BT_ROW   72
#define BT_BYTES (128 * BT_ROW * 2)          // 18432
#define OUTS_OFF (A_BYTES + 2 * BT_BYTES)    // 104448
#define SMEM_BYTES (OUTS_OFF + 4 * BSAMP * 8 * 4)   // 112640

__global__ __launch_bounds__(TPB, 2)
void qsim_kernel(const float* __restrict__ x, float* __restrict__ out) {
    extern __shared__ char smem[];
    uint16_t* A = (uint16_t*)smem;
    float* outs = (float*)(smem + OUTS_OFF);             // [4 wn][64][8]

    const uint32_t smem_u32 = (uint32_t)__cvta_generic_to_shared(smem);
    const uint32_t A_u32    = smem_u32;
    const uint32_t Bt_u32[2] = { smem_u32 + A_BYTES, smem_u32 + A_BYTES + BT_BYTES };
    uint16_t* Bt_gen[2] = { (uint16_t*)(smem + A_BYTES),
                            (uint16_t*)(smem + A_BYTES + BT_BYTES) };

    const int tid  = threadIdx.x;
    const int smp0 = blockIdx.x * BSAMP;

#pragma unroll
    for (int z = 0; z < 2; z++)
        ((float4*)outs)[tid + z * 256] = make_float4(0.f, 0.f, 0.f, 0.f);

    // tile loader: phase nc, k' chunk kc (64 cols) for 128 n-rows
    auto issue_tile = [&](int nc, int kc, int buf) {
        const uint16_t* src =
            reinterpret_cast<const uint16_t*>(g_Bp) + (size_t)(nc * 128) * KP + kc * 64;
        uint16_t* dst = Bt_gen[buf];
#pragma unroll
        for (int c = 0; c < 4; c++) {
            int idx = tid + c * 256;          // 16B granule id, 0..1023
            int r = idx >> 3, gg = idx & 7;
            cp_async16((uint32_t)__cvta_generic_to_shared(dst + r * BT_ROW + gg * 8),
                       src + (size_t)r * KP + gg * 8);
        }
        cp_async_commit();
    };

    issue_tile(0, 0, 0);   // prefetch first tile; lands while we build A

    // ---- Phase 1: build A (4 threads per sample), bf16 split h/m ----
    {
        int s = tid >> 2, q = tid & 3;      // q = amplitude bits 7..6
        const float* xp = x + (size_t)(smp0 + s) * 8;
        float fc[8], fs[8];
#pragma unroll
        for (int w = 0; w < 8; w++) {
            float h = 0.5f * xp[w];
            fc[w] = cosf(h);
            fs[w] = sinf(h);
        }
        float f01 = ((q & 2) ? fs[0] : fc[0]) * ((q & 1) ? fs[1] : fc[1]);
#pragma unroll
        for (int jj = 0; jj < 64; jj++) {
            float r = f01;
            r *= (jj & 32) ? fs[2] : fc[2];
            r *= (jj & 16) ? fs[3] : fc[3];
            r *= (jj &  8) ? fs[4] : fc[4];
            r *= (jj &  4) ? fs[5] : fc[5];
            r *= (jj &  2) ? fs[6] : fc[6];
            r *= (jj &  1) ? fs[7] : fc[7];
            __nv_bfloat16 h, m;
            bsplit(r, h, m);
            int k = q * 64 + jj;
            A[0 * A_SELSZ + s * A_ROW + k] = ((uint16_t*)&h)[0];
            A[1 * A_SELSZ + s * A_ROW + k] = ((uint16_t*)&m)[0];
        }
    }

    const int lane = tid & 31;
    const int g = lane >> 2, t = lane & 3;
    const int wid = tid >> 5;
    const int wm = wid >> 2;          // 0..1  (m-rows wm*32)
    const int wn = wid & 3;           // 0..3  (n-cols wn*32 within phase)

    // lane-fixed pieces of ldmatrix addressing (passed R8/R10/R11/R13)
    const int a_rowlane = wm * 32 + (lane & 15);           // + mf*16
    const int a_collane = (lane >> 4) << 3;                // 0 or 8
    const int b_rowlane = wn * 32 + (lane & 7) + ((lane >> 4) << 3);  // + np*16
    const int b_collane = ((lane >> 3) & 1) << 3;          // 0 or 8

    const int NKC = KP / 64;   // 12

    for (int nc = 0; nc < 4; nc++) {
        float acc[2][4][4];
#pragma unroll
        for (int mf = 0; mf < 2; mf++)
#pragma unroll
            for (int nf = 0; nf < 4; nf++)
#pragma unroll
                for (int d = 0; d < 4; d++) acc[mf][nf][d] = 0.0f;

        for (int kc = 0; kc < NKC; kc++) {
            cp_async_wait<0>();               // tile kc landed (this thread)
            __syncthreads();                  // all warps done with other buffer
            if (kc < NKC - 1)
                issue_tile(nc, kc + 1, (kc + 1) & 1);   // overlaps compute(kc)
            else if (nc < 3)
                issue_tile(nc + 1, 0, 0);               // prefetch next phase

            const uint32_t Bs = Bt_u32[kc & 1];

            if (kc < 8) {
                // interleaved hh/hm chunk: B cols = [Bh lo16|Bh hi16|Bm lo16|Bm hi16]
                // A frags (asel=0) at ak = kc*32 (half 0) and kc*32+16 (half 1),
                // loaded ONCE and reused for both Bh and Bm (ks&1 selects half).
                uint32_t a2[2][2][4];   // [half][mf][4]
#pragma unroll
                for (int half = 0; half < 2; half++) {
                    const int ak = kc * 32 + half * 16;
#pragma unroll
                    for (int mf = 0; mf < 2; mf++) {
                        uint32_t addr = A_u32 +
                            (((a_rowlane + mf * 16) * A_ROW + ak + a_collane) << 1);
                        ldsm_x4(a2[half][mf][0], a2[half][mf][1],
                                a2[half][mf][2], a2[half][mf][3], addr);
                    }
                }
#pragma unroll
                for (int ks = 0; ks < 4; ks++) {
                    const int half = ks & 1;
                    uint32_t bf[2][4];
#pragma unroll
                    for (int np = 0; np < 2; np++) {
                        uint32_t addr = Bs +
                            (((b_rowlane + np * 16) * BT_ROW + ks * 16 + b_collane) << 1);
                        ldsm_x4(bf[np][0], bf[np][1], bf[np][2], bf[np][3], addr);
                    }
#pragma unroll
                    for (int mf = 0; mf < 2; mf++)
#pragma unroll
                        for (int np = 0; np < 2; np++) {
                            mma_bf16(acc[mf][2 * np],     a2[half][mf], bf[np][0], bf[np][1]);
                            mma_bf16(acc[mf][2 * np + 1], a2[half][mf], bf[np][2], bf[np][3]);
                        }
                }
            } else {
                // Am*Bh chunk: ak = (kc-8)*64 + ks*16, asel=1 (as R13)
#pragma unroll
                for (int ks = 0; ks < 4; ks++) {
                    const int ak = (kc - 8) * 64 + ks * 16;
                    uint32_t a[2][4];
#pragma unroll
                    for (int mf = 0; mf < 2; mf++) {
                        uint32_t addr = A_u32 +
                            ((A_SELSZ + (a_rowlane + mf * 16) * A_ROW + ak + a_collane) << 1);
                        ldsm_x4(a[mf][0], a[mf][1], a[mf][2], a[mf][3], addr);
                    }
                    uint32_t bf[2][4];
#pragma unroll
                    for (int np = 0; np < 2; np++) {
                        uint32_t addr = Bs +
                            (((b_rowlane + np * 16) * BT_ROW + ks * 16 + b_collane) << 1);
                        ldsm_x4(bf[np][0], bf[np][1], bf[np][2], bf[np][3], addr);
                    }
#pragma unroll
                    for (int mf = 0; mf < 2; mf++)
#pragma unroll
                        for (int np = 0; np < 2; np++) {
                            mma_bf16(acc[mf][2 * np],     a[mf], bf[np][0], bf[np][1]);
                            mma_bf16(acc[mf][2 * np + 1], a[mf], bf[np][2], bf[np][3]);
                        }
                }
            }
            // no trailing barrier: next iteration's top barrier protects reuse
        }

        // ---- epilogue: P = re^2+im^2, Walsh signs, reduce over t ----
#pragma unroll
        for (int mf = 0; mf < 2; mf++) {
            float oa[2][8];
#pragma unroll
            for (int r = 0; r < 2; r++)
#pragma unroll
                for (int k = 0; k < 8; k++) oa[r][k] = 0.0f;

#pragma unroll
            for (int nf = 0; nf < 4; nf++) {
                int i = nc * 64 + wn * 16 + nf * 4 + t;   // amplitude index
                float Pg  = acc[mf][nf][0] * acc[mf][nf][0] + acc[mf][nf][1] * acc[mf][nf][1];
                float Pg8 = acc[mf][nf][2] * acc[mf][nf][2] + acc[mf][nf][3] * acc[mf][nf][3];
#pragma unroll
                for (int k = 0; k < 8; k++) {
                    float s = ((i >> (7 - k)) & 1) ? -1.0f : 1.0f;
                    oa[0][k] += s * Pg;
                    oa[1][k] += s * Pg8;
                }
            }
#pragma unroll
            for (int r = 0; r < 2; r++)
#pragma unroll
                for (int k = 0; k < 8; k++) {
                    float v = oa[r][k];
                    v += __shfl_xor_sync(0xffffffffu, v, 1);
                    v += __shfl_xor_sync(0xffffffffu, v, 2);
                    if (t == 0) {
                        int row = wm * 32 + mf * 16 + g + 8 * r;
                        outs[(wn * BSAMP + row) * 8 + k] += v;   // unique writer
                    }
                }
        }
    }

    __syncthreads();
    // sum 4 wn-partials, write out (threads 0..127, one float4 each)
    if (tid < 128) {
        float4 v0 = ((const float4*)outs)[tid];
        float4 v1 = ((const float4*)outs)[tid + 128];
        float4 v2 = ((const float4*)outs)[tid + 256];
        float4 v3 = ((const float4*)outs)[tid + 384];
        float4 v = make_float4(v0.x + v1.x + v2.x + v3.x,
                               v0.y + v1.y + v2.y + v3.y,
                               v0.z + v1.z + v2.z + v3.z,
                               v0.w + v1.w + v2.w + v3.w);
        ((float4*)(out + (size_t)smp0 * 8))[tid] = v;
    }
}

// ---------------------------------------------------------------------------
// GATE_OPS via the exact reference mechanism (numpy subprocess). PASSED R4-R15.
// ---------------------------------------------------------------------------
static const char* PY_SNIPPET =
    "import numpy as np\n"
    "r = np.random.default_rng(42)\n"
    "for _ in range(20):\n"
    "    g = int(r.integers(0, 4))\n"
    "    if g == 3:\n"
    "        c, t = r.choice(8, size=2, replace=False)\n"
    "        print(3, int(c), int(t))\n"
    "    else:\n"
    "        print(g, int(r.integers(0, 8)), -1)\n";

static bool compute_gate_ops_python(OpsParam& ops, const char* interp) {
    char cmd[2048];
    snprintf(cmd, sizeof(cmd), "%s -c '%s' 2>/dev/null", interp, PY_SNIPPET);
    FILE* f = popen(cmd, "r");
    if (!f) return false;
    int n = 0;
    while (n < NRAND) {
        int g, a, b;
        if (fscanf(f, "%d %d %d", &g, &a, &b) != 3) break;
        if (g < 0 || g > 3 || a < 0 || a > 7 || (g == 3 && (b < 0 || b > 7))) break;
        ops.kind[n] = g; ops.wa[n] = a; ops.wb[n] = b;
        n++;
    }
    pclose(f);
    return n == NRAND;
}

namespace nprng {

struct PCG64 { __uint128_t state, inc; int has32; uint32_t buf32; };

static const __uint128_t PCG_MULT =
    (((__uint128_t)2549297995355413924ULL) << 64) | 4865540595714422341ULL;

static uint64_t next64(PCG64& r) {
    r.state = r.state * PCG_MULT + r.inc;
    uint64_t hi = (uint64_t)(r.state >> 64), lo = (uint64_t)r.state;
    uint64_t xv = hi ^ lo;
    unsigned rot = (unsigned)(r.state >> 122);
    return (xv >> rot) | (xv << ((64u - rot) & 63u));
}
static uint32_t next32(PCG64& r) {
    if (r.has32) { r.has32 = 0; return r.buf32; }
    uint64_t v = next64(r);
    r.has32 = 1;
    r.buf32 = (uint32_t)(v >> 32);
    return (uint32_t)v;
}
static void seedseq42(uint64_t out[4]) {
    const uint32_t XSH = 16;
    uint32_t pool[4];
    uint32_t hc = 0x43b0d7e5u;
    auto hashmix = [&](uint32_t v) {
        v ^= hc; hc *= 0x931e8875u; v *= hc; v ^= v >> XSH; return v;
    };
    auto mixf = [&](uint32_t xx, uint32_t yy) {
        uint32_t rr = (xx * 0xca01f9ddu) ^ (yy * 0x4973f715u);
        rr ^= rr >> XSH; return rr;
    };
    pool[0] = hashmix(42u);
    pool[1] = hashmix(0u);
    pool[2] = hashmix(0u);
    pool[3] = hashmix(0u);
    for (int src = 0; src < 4; src++)
        for (int dst = 0; dst < 4; dst++)
            if (src != dst) pool[dst] = mixf(pool[dst], hashmix(pool[src]));
    uint32_t hb = 0x8b51f9ddu;
    uint32_t w[8];
    for (int i = 0; i < 8; i++) {
        uint32_t v = pool[i & 3];
        v ^= hb; hb *= 0x58f38dedu; v *= hb; v ^= v >> XSH;
        w[i] = v;
    }
    for (int k = 0; k < 4; k++)
        out[k] = (uint64_t)w[2 * k] | ((uint64_t)w[2 * k + 1] << 32);
}
static void init42(PCG64& r) {
    uint64_t s4[4];
    seedseq42(s4);
    __uint128_t initstate = (((__uint128_t)s4[0]) << 64) | s4[1];
    __uint128_t initseq   = (((__uint128_t)s4[2]) << 64) | s4[3];
    r.state = 0;
    r.inc   = (initseq << 1) | 1;
    r.state = r.state * PCG_MULT + r.inc;
    r.state += initstate;
    r.state = r.state * PCG_MULT + r.inc;
    r.has32 = 0;
    r.buf32 = 0;
}
static uint64_t lemire32(PCG64& r, uint32_t rng) {
    uint32_t rng_excl = rng + 1;
    uint64_t m = (uint64_t)next32(r) * (uint64_t)rng_excl;
    uint32_t leftover = (uint32_t)m;
    if (leftover < rng_excl) {
        uint32_t threshold = (uint32_t)((0xFFFFFFFFu - rng) % rng_excl);
        while (leftover < threshold) {
            m = (uint64_t)next32(r) * (uint64_t)rng_excl;
            leftover = (uint32_t)m;
        }
    }
    return (uint64_t)(m >> 32);
}
} // namespace nprng

static void compute_gate_ops_cpp(OpsParam& ops) {
    nprng::PCG64 r;
    nprng::init42(r);
    for (int p = 0; p < NRAND; p++) {
        int g = (int)nprng::lemire32(r, 3);
        if (g == 3) {
            uint64_t v6 = nprng::lemire32(r, 6);
            uint64_t v7 = nprng::lemire32(r, 7);
            uint64_t i0 = v6;
            uint64_t i1 = (v7 == v6) ? 7 : v7;
            uint64_t js = nprng::lemire32(r, 1);
            if (js == 0) { uint64_t t = i0; i0 = i1; i1 = t; }
            ops.kind[p] = 3;
            ops.wa[p] = (int)i0;
            ops.wb[p] = (int)i1;
        } else {
            ops.kind[p] = g;
            ops.wa[p] = (int)nprng::lemire32(r, 7);
            ops.wb[p] = -1;
        }
    }
}

extern "C" void kernel_launch(void* const* d_in, const int* in_sizes, int n_in,
                              void* d_out, int out_size) {
    const float* x  = nullptr;
    const float* rx = nullptr;
    const float* rp = nullptr;
    for (int i = 0; i < n_in; i++) {
        if (in_sizes[i] == 8)       rx = (const float*)d_in[i];
        else if (in_sizes[i] == 20) rp = (const float*)d_in[i];
        else                        x  = (const float*)d_in[i];
    }
    if (!x)  x  = (const float*)d_in[0];
    if (!rx) rx = (const float*)d_in[1];
    if (!rp) rp = (const float*)d_in[2];
    float* out = (float*)d_out;
    (void)out_size;

    OpsParam ops;
    bool ok = compute_gate_ops_python(ops, "python3");
    if (!ok) ok = compute_gate_ops_python(ops, "python");
    if (!ok) {
        fprintf(stderr, "[qsim] python GATE_OPS derivation FAILED -> C++ fallback\n");
        compute_gate_ops_cpp(ops);
    }

    for (int w = 0; w < 8; w++) {
        ops.kind[NRAND + w] = 0;
        ops.wa[NRAND + w] = w;
        ops.wb[NRAND + w] = -1;
    }

    cudaFuncSetAttribute(qsim_kernel, cudaFuncAttributeMaxDynamicSharedMemorySize,
                         SMEM_BYTES);

    build_W_kernel<<<QDIM, 128>>>(rx, rp, ops);
    qsim_kernel<<<NSAMP / BSAMP, TPB, SMEM_BYTES>>>(x, out);
}